// round 2
// baseline (speedup 1.0000x reference)
#include <cuda_runtime.h>

#define Bn 64
#define Tn 2048
#define In 128
#define Hn 256
#define NPAIR 2                 // output column-pairs per CTA
#define GCTA  (Hn / NPAIR)      // 128 CTAs
#define THREADS 128

typedef unsigned long long u64;

// ---------------- device state (scratch; no allocations allowed) ----------------
__device__ float g_h0[2][Bn][Hn];
__device__ float g_h1[2][Bn][Hn];
__device__ unsigned g_count;

// ---------------- helpers ----------------
__device__ __forceinline__ void fma2(u64 &d, const u64 a, const u64 b) {
    // packed fp32x2 FMA (SASS FFMA2) — PTX-only form on sm_103a
    asm("fma.rn.f32x2 %0, %1, %2, %0;" : "+l"(d) : "l"(a), "l"(b));
}

__device__ __forceinline__ float sum2(u64 v) {
    float lo = __uint_as_float((unsigned)(v & 0xffffffffull));
    float hi = __uint_as_float((unsigned)(v >> 32));
    return lo + hi;
}

__device__ __forceinline__ float sigmoidf_(float v) {
    return 1.0f / (1.0f + __expf(-v));
}

// Accumulate over a K-segment: two input rows (global), two weight columns (smem),
// packed even/odd accumulation in f32x2.
template<int KL>
__device__ __forceinline__ void accum_seg(
    const float* __restrict__ in0, const float* __restrict__ in1,
    const float* __restrict__ wc,  const float* __restrict__ wa,
    u64 &c0, u64 &a0, u64 &c1, u64 &a1)
{
    const ulonglong2* p0 = (const ulonglong2*)in0;
    const ulonglong2* p1 = (const ulonglong2*)in1;
    const ulonglong2* pc = (const ulonglong2*)wc;
    const ulonglong2* pa = (const ulonglong2*)wa;
#pragma unroll 8
    for (int i = 0; i < KL / 4; i++) {
        ulonglong2 v0 = p0[i];
        ulonglong2 v1 = p1[i];
        ulonglong2 wcv = pc[i];
        ulonglong2 wav = pa[i];
        fma2(c0, v0.x, wcv.x); fma2(c0, v0.y, wcv.y);
        fma2(a0, v0.x, wav.x); fma2(a0, v0.y, wav.y);
        fma2(c1, v1.x, wcv.x); fma2(c1, v1.y, wcv.y);
        fma2(a1, v1.x, wav.x); fma2(a1, v1.y, wav.y);
    }
}

// Software grid barrier: monotonic counter, release (fence+atomic) / acquire (poll+fence).
__device__ __forceinline__ void grid_barrier(unsigned target) {
    __syncthreads();
    if (threadIdx.x == 0) {
        __threadfence();
        atomicAdd(&g_count, 1u);
        while (*((volatile unsigned*)&g_count) < target) { }
        __threadfence();
    }
    __syncthreads();
}

// ---------------- init: reset barrier + zero hidden state (runs every replay) ----------------
__global__ void init_kernel() {
    int i = blockIdx.x * blockDim.x + threadIdx.x;
    if (i == 0) g_count = 0u;
    float* h0 = &g_h0[0][0][0];
    float* h1 = &g_h1[0][0][0];
    const int n = 2 * Bn * Hn;
    for (int j = i; j < n; j += gridDim.x * blockDim.x) {
        h0[j] = 0.0f;
        h1[j] = 0.0f;
    }
}

// ---------------- persistent recurrent kernel ----------------
__global__ void __launch_bounds__(THREADS, 1) rnn_persistent(
    const float* __restrict__ x,
    const float* __restrict__ Wih0, const float* __restrict__ Whh0, const float* __restrict__ bh0,
    const float* __restrict__ Wax0, const float* __restrict__ Wah0, const float* __restrict__ ba0,
    const float* __restrict__ Wih1, const float* __restrict__ Whh1, const float* __restrict__ bh1,
    const float* __restrict__ Wax1, const float* __restrict__ Wah1, const float* __restrict__ ba1,
    float* __restrict__ out)
{
    // Weight columns (column-major over K) for this CTA's NPAIR output columns.
    // Layer 0 fused K = 384:  k<128 -> x-proj (Wih0/Wax0), k>=128 -> h0-proj (Whh0/Wah0)
    // Layer 1 fused K = 512:  k<256 -> cur-proj (Wih1/Wax1), k>=256 -> h1-proj (Whh1/Wah1)
    __shared__ float wAc[NPAIR][384];
    __shared__ float wAa[NPAIR][384];
    __shared__ float wBc[NPAIR][512];
    __shared__ float wBa[NPAIR][512];
    __shared__ float red[64][4];
    __shared__ float biasv[4][NPAIR];

    const int tid  = threadIdx.x;
    const int cta  = blockIdx.x;
    const int col0 = cta * NPAIR;

    // gather weights into smem (one-time)
    for (int idx = tid; idx < NPAIR * 384; idx += THREADS) {
        int p = idx / 384, k = idx % 384;
        int col = col0 + p;
        wAc[p][k] = (k < In) ? Wih0[k * Hn + col] : Whh0[(k - In) * Hn + col];
        wAa[p][k] = (k < In) ? Wax0[k * Hn + col] : Wah0[(k - In) * Hn + col];
    }
    for (int idx = tid; idx < NPAIR * 512; idx += THREADS) {
        int p = idx / 512, k = idx % 512;
        int col = col0 + p;
        wBc[p][k] = (k < Hn) ? Wih1[k * Hn + col] : Whh1[(k - Hn) * Hn + col];
        wBa[p][k] = (k < Hn) ? Wax1[k * Hn + col] : Wah1[(k - Hn) * Hn + col];
    }
    if (tid < NPAIR) {
        int col = col0 + tid;
        biasv[0][tid] = bh0[col];
        biasv[1][tid] = ba0[col];
        biasv[2][tid] = bh1[col];
        biasv[3][tid] = ba1[col];
    }
    __syncthreads();

    // thread decomposition: ks = K-split half, slot -> (rowgroup, pair)
    const int ks   = tid >> 6;        // 0 or 1
    const int slot = tid & 63;        // 0..63
    const int p    = slot & (NPAIR - 1);
    const int rg   = slot >> 1;       // 0..31
    const int r0   = rg * 2;
    const int r1   = r0 + 1;
    const int col  = col0 + p;

    // ---- layer 0 at step s: h0_new = a*tanh(cand) + (1-a)*h0 ----
    auto phaseA = [&](int s) {
        const float* h0prev = &g_h0[(s + 1) & 1][0][0];
        float*       h0next = &g_h0[s & 1][0][0];
        u64 c0 = 0, a0 = 0, c1 = 0, a1 = 0;
        if (ks == 0) {
            accum_seg<128>(x + (r0 * Tn + s) * In, x + (r1 * Tn + s) * In,
                           wAc[p], wAa[p], c0, a0, c1, a1);
            accum_seg<64>(h0prev + r0 * Hn, h0prev + r1 * Hn,
                          wAc[p] + 128, wAa[p] + 128, c0, a0, c1, a1);
        } else {
            accum_seg<192>(h0prev + r0 * Hn + 64, h0prev + r1 * Hn + 64,
                           wAc[p] + 192, wAa[p] + 192, c0, a0, c1, a1);
        }
        __syncthreads();
        if (ks == 1) {
            red[slot][0] = sum2(c0); red[slot][1] = sum2(a0);
            red[slot][2] = sum2(c1); red[slot][3] = sum2(a1);
        }
        __syncthreads();
        if (ks == 0) {
            float cc0 = sum2(c0) + red[slot][0] + biasv[0][p];
            float aa0 = sum2(a0) + red[slot][1] + biasv[1][p];
            float cc1 = sum2(c1) + red[slot][2] + biasv[0][p];
            float aa1 = sum2(a1) + red[slot][3] + biasv[1][p];
            float al0 = sigmoidf_(aa0), al1 = sigmoidf_(aa1);
            float t0 = tanhf(cc0),      t1 = tanhf(cc1);
            float hp0 = h0prev[r0 * Hn + col];
            float hp1 = h0prev[r1 * Hn + col];
            h0next[r0 * Hn + col] = al0 * t0 + (1.0f - al0) * hp0;
            h0next[r1 * Hn + col] = al1 * t1 + (1.0f - al1) * hp1;
        }
    };

    // ---- layer 1 at step t: writes h1 state and the [B,T,H] output ----
    auto phaseB = [&](int t) {
        const float* cur    = &g_h0[t & 1][0][0];
        const float* h1prev = &g_h1[(t + 1) & 1][0][0];
        float*       h1next = &g_h1[t & 1][0][0];
        u64 c0 = 0, a0 = 0, c1 = 0, a1 = 0;
        if (ks == 0) {
            accum_seg<256>(cur + r0 * Hn, cur + r1 * Hn,
                           wBc[p], wBa[p], c0, a0, c1, a1);
        } else {
            accum_seg<256>(h1prev + r0 * Hn, h1prev + r1 * Hn,
                           wBc[p] + 256, wBa[p] + 256, c0, a0, c1, a1);
        }
        __syncthreads();
        if (ks == 1) {
            red[slot][0] = sum2(c0); red[slot][1] = sum2(a0);
            red[slot][2] = sum2(c1); red[slot][3] = sum2(a1);
        }
        __syncthreads();
        if (ks == 0) {
            float cc0 = sum2(c0) + red[slot][0] + biasv[2][p];
            float aa0 = sum2(a0) + red[slot][1] + biasv[3][p];
            float cc1 = sum2(c1) + red[slot][2] + biasv[2][p];
            float aa1 = sum2(a1) + red[slot][3] + biasv[3][p];
            float al0 = sigmoidf_(aa0), al1 = sigmoidf_(aa1);
            float t0 = tanhf(cc0),      t1 = tanhf(cc1);
            float hp0 = h1prev[r0 * Hn + col];
            float hp1 = h1prev[r1 * Hn + col];
            float hn0 = al0 * t0 + (1.0f - al0) * hp0;
            float hn1 = al1 * t1 + (1.0f - al1) * hp1;
            h1next[r0 * Hn + col] = hn0;
            h1next[r1 * Hn + col] = hn1;
            out[(r0 * Tn + t) * Hn + col] = hn0;
            out[(r1 * Tn + t) * Hn + col] = hn1;
        }
    };

    // ---- main sequential loop: one grid barrier per timestep ----
    phaseA(0);
    unsigned bar = 1;
    grid_barrier(GCTA * bar); bar++;
    for (int t = 0; t < Tn; t++) {
        phaseB(t);
        if (t < Tn - 1) phaseA(t + 1);
        grid_barrier(GCTA * bar); bar++;
    }

    // ---- h_final: [L=2][B][H] appended after outputs ----
    float* hf = out + (size_t)Bn * Tn * Hn;
    const float* h0f = &g_h0[(Tn - 1) & 1][0][0];
    const float* h1f = &g_h1[(Tn - 1) & 1][0][0];
    for (int idx = tid; idx < Bn * NPAIR; idx += THREADS) {
        int r = idx / NPAIR;
        int pp = idx % NPAIR;
        int c = col0 + pp;
        hf[r * Hn + c]           = h0f[r * Hn + c];
        hf[Bn * Hn + r * Hn + c] = h1f[r * Hn + c];
    }
}

// ---------------- launch ----------------
extern "C" void kernel_launch(void* const* d_in, const int* in_sizes, int n_in,
                              void* d_out, int out_size) {
    const float* x    = (const float*)d_in[0];
    const float* Wih0 = (const float*)d_in[1];
    const float* Whh0 = (const float*)d_in[2];
    const float* bh0  = (const float*)d_in[3];
    const float* Wax0 = (const float*)d_in[4];
    const float* Wah0 = (const float*)d_in[5];
    const float* ba0  = (const float*)d_in[6];
    const float* Wih1 = (const float*)d_in[7];
    const float* Whh1 = (const float*)d_in[8];
    const float* bh1  = (const float*)d_in[9];
    const float* Wax1 = (const float*)d_in[10];
    const float* Wah1 = (const float*)d_in[11];
    const float* ba1  = (const float*)d_in[12];
    float* out = (float*)d_out;

    init_kernel<<<64, 256>>>();
    rnn_persistent<<<GCTA, THREADS>>>(x,
        Wih0, Whh0, bh0, Wax0, Wah0, ba0,
        Wih1, Whh1, bh1, Wax1, Wah1, ba1,
        out);
}

// round 3
// speedup vs baseline: 2.0123x; 2.0123x over previous
#include <cuda_runtime.h>

#define Bn 64
#define Tn 2048
#define In 128
#define Hn 256
#define THREADS 256
#define NCOL 8                  // columns per CTA
#define NBAT 16                 // batches per CTA
#define NCG  (Hn / NCOL)        // 32 col-groups
#define NBG  (Bn / NBAT)        // 4 batch-groups
#define GCTA (NCG * NBG)        // 128 CTAs
#define KA 384                  // layer0 fused K (x:128 + h0:256)
#define KB 512                  // layer1 fused K (h0:256 + h1:256)

typedef unsigned long long u64;

// ---------------- device scratch (static; no allocations) ----------------
__device__ __align__(256) float g_xT[Tn][In][Bn];     // x transposed: [t][k][b]
__device__ __align__(256) float g_h0T[2][Hn][Bn];     // h0 double-buffered, [k][b]
__device__ __align__(256) float g_h1T[2][Hn][Bn];
__device__ unsigned g_count;

// ---------------- packed f32x2 helpers ----------------
__device__ __forceinline__ void fma2(u64 &d, u64 a, u64 b) {
    asm("fma.rn.f32x2 %0, %1, %2, %0;" : "+l"(d) : "l"(a), "l"(b));
}
__device__ __forceinline__ u64 add2(u64 a, u64 b) {
    u64 d; asm("add.rn.f32x2 %0, %1, %2;" : "=l"(d) : "l"(a), "l"(b)); return d;
}
__device__ __forceinline__ u64 dup2(float f) {
    u64 d; asm("mov.b64 %0, {%1, %1};" : "=l"(d) : "f"(f)); return d;
}
__device__ __forceinline__ float lo2(u64 v) { return __uint_as_float((unsigned)(v & 0xffffffffull)); }
__device__ __forceinline__ float hi2(u64 v) { return __uint_as_float((unsigned)(v >> 32)); }

// 16B L2-only load (state written by other SMs each step -> must bypass L1)
__device__ __forceinline__ void ldcg2(const float* p, u64 &a, u64 &b) {
    asm volatile("ld.global.cg.v2.u64 {%0, %1}, [%2];" : "=l"(a), "=l"(b) : "l"(p));
}

// ---------------- grid barrier ----------------
__device__ __forceinline__ void grid_barrier(unsigned target) {
    __syncthreads();
    if (threadIdx.x == 0) {
        __threadfence();
        atomicAdd(&g_count, 1u);
        while (*((volatile unsigned*)&g_count) < target) { }
        __threadfence();
    }
    __syncthreads();
}

// ---------------- accumulate over a K-slice ----------------
// lane's state: 4 consecutive batches at boff. weights: pre-dup'd {wc,wc},{wa,wa}.
template<int KN>
__device__ __forceinline__ void accum_g(
    const float* __restrict__ st, const ulonglong2* __restrict__ w,
    u64 &cL, u64 &cH, u64 &aL, u64 &aH)
{
#pragma unroll 8
    for (int i = 0; i < KN; i++) {
        u64 sL, sH;
        ldcg2(st + i * Bn, sL, sH);
        ulonglong2 wv = w[i * NCOL];
        fma2(cL, sL, wv.x); fma2(cH, sH, wv.x);
        fma2(aL, sL, wv.y); fma2(aH, sH, wv.y);
    }
}

// ---------------- prep: transpose x, zero states, reset barrier ----------------
__global__ void prep_kernel(const float* __restrict__ x) {
    __shared__ float s[In * 65];
    const int t = blockIdx.x;
    const int tid = threadIdx.x;
    for (int idx = tid; idx < Bn * In; idx += THREADS) {
        int i = idx & (In - 1), b = idx >> 7;
        s[i * 65 + b] = x[((size_t)b * Tn + t) * In + i];
    }
    __syncthreads();
    for (int idx = tid; idx < In * Bn; idx += THREADS) {
        int b = idx & (Bn - 1), i = idx >> 6;
        g_xT[t][i][b] = s[i * 65 + b];
    }
    if (t == 0 && tid == 0) g_count = 0u;
    if (t < 4) {
        float* z = (t < 2) ? &g_h0T[t][0][0] : &g_h1T[t - 2][0][0];
        for (int i = tid; i < Hn * Bn; i += THREADS) z[i] = 0.0f;
    }
}

// ---------------- persistent RNN kernel ----------------
__global__ void __launch_bounds__(THREADS, 1) rnn_kernel(
    const float* __restrict__ Wih0, const float* __restrict__ Whh0,
    const float* __restrict__ bh0,  const float* __restrict__ Wax0,
    const float* __restrict__ Wah0, const float* __restrict__ ba0,
    const float* __restrict__ Wih1, const float* __restrict__ Whh1,
    const float* __restrict__ bh1,  const float* __restrict__ Wax1,
    const float* __restrict__ Wah1, const float* __restrict__ ba1,
    float* __restrict__ out)
{
    extern __shared__ ulonglong2 smbase[];
    ulonglong2* wA    = smbase;                   // [KA*NCOL] {dup(wc), dup(wa)}
    ulonglong2* wB    = wA + KA * NCOL;           // [KB*NCOL]
    u64*        red   = (u64*)(wB + KB * NCOL);   // [256 threads][8]
    u64*        sbias = red + 256 * 8;            // [4][NCOL] dup'd

    const int tid  = threadIdx.x;
    const int cg   = blockIdx.x & (NCG - 1);
    const int bg   = blockIdx.x >> 5;
    const int col0 = cg * NCOL;
    const int b0g  = bg * NBAT;

    // ---- one-time weight gather (k-major, dup-packed) ----
    for (int idx = tid; idx < KA * NCOL; idx += THREADS) {
        int k = idx >> 3, c = idx & 7, C = col0 + c;
        float wc = (k < In) ? Wih0[k * Hn + C] : Whh0[(k - In) * Hn + C];
        float wa = (k < In) ? Wax0[k * Hn + C] : Wah0[(k - In) * Hn + C];
        wA[idx] = make_ulonglong2(dup2(wc), dup2(wa));
    }
    for (int idx = tid; idx < KB * NCOL; idx += THREADS) {
        int k = idx >> 3, c = idx & 7, C = col0 + c;
        float wc = (k < Hn) ? Wih1[k * Hn + C] : Whh1[(k - Hn) * Hn + C];
        float wa = (k < Hn) ? Wax1[k * Hn + C] : Wah1[(k - Hn) * Hn + C];
        wB[idx] = make_ulonglong2(dup2(wc), dup2(wa));
    }
    if (tid < 4 * NCOL) {
        int c = tid & 7, sel = tid >> 3;  // 0=bh0 1=ba0 2=bh1 3=ba1
        const float* bp = (sel == 0) ? bh0 : (sel == 1) ? ba0 : (sel == 2) ? bh1 : ba1;
        sbias[sel * NCOL + c] = dup2(bp[col0 + c]);
    }
    __syncthreads();

    // ---- accumulation mapping: warp = K-slice, lane = (col, batch-quad) ----
    const int w    = tid >> 5;
    const int ln   = tid & 31;
    const int acol = ln >> 2;
    const int bp2  = ln & 3;
    const int boff = b0g + bp2 * 4;
    const int kxA  = w * 16;     // A x-part slice
    const int khA  = w * 32;     // A h0-part slice
    const int khB  = w * 32;     // B slices (h0 and h1)

    // ---- epilogue mapping (tid < 128): (phase, col, batch-pair) ----
    const int ep    = tid >> 6;
    const int er    = tid & 63;
    const int ecol  = er >> 3;
    const int ebp   = er & 7;
    const int elane = ecol * 4 + (ebp >> 1);
    const int ehalf = ebp & 1;
    const int eb    = b0g + ebp * 2;
    const int eC    = col0 + ecol;
    float hpA0 = 0.f, hpA1 = 0.f, hpB0 = 0.f, hpB1 = 0.f;

    unsigned bar = 1;

    // iteration t: phase B computes h1[t] (t>=0); phase A computes h0[t+1] (t+1<Tn)
    for (int t = -1; t < Tn; t++) {
        const int s = t + 1;
        const bool doA = (s < Tn);
        const bool doB = (t >= 0);
        u64 AcL = 0, AcH = 0, AaL = 0, AaH = 0;
        u64 BcL = 0, BcH = 0, BaL = 0, BaH = 0;

        if (doA) {
            accum_g<16>(&g_xT[s][kxA][boff],          wA + kxA * NCOL + acol,        AcL, AcH, AaL, AaH);
            accum_g<32>(&g_h0T[(s + 1) & 1][khA][boff], wA + (In + khA) * NCOL + acol, AcL, AcH, AaL, AaH);
        }
        if (doB) {
            accum_g<32>(&g_h0T[t & 1][khB][boff],       wB + khB * NCOL + acol,        BcL, BcH, BaL, BaH);
            accum_g<32>(&g_h1T[(t + 1) & 1][khB][boff], wB + (Hn + khB) * NCOL + acol, BcL, BcH, BaL, BaH);
        }

        // stage partials: per thread 4x ulonglong2 = [half0(c,a) A][half1 A][half0 B][half1 B]
        {
            ulonglong2* rr = (ulonglong2*)(red + (tid << 3));
            rr[0] = make_ulonglong2(AcL, AaL);
            rr[1] = make_ulonglong2(AcH, AaH);
            rr[2] = make_ulonglong2(BcL, BaL);
            rr[3] = make_ulonglong2(BcH, BaH);
        }
        __syncthreads();

        if (tid < 128 && (ep ? doB : doA)) {
            const ulonglong2* rbase = (const ulonglong2*)red;
            const int off = ep * 2 + ehalf;
            u64 c = 0, a = 0;
#pragma unroll
            for (int ww = 0; ww < 8; ww++) {
                ulonglong2 v = rbase[(ww * 32 + elane) * 4 + off];
                c = add2(c, v.x);
                a = add2(a, v.y);
            }
            c = add2(c, sbias[(ep * 2 + 0) * NCOL + ecol]);
            a = add2(a, sbias[(ep * 2 + 1) * NCOL + ecol]);
            float cx = lo2(c), cy = hi2(c);
            float ax = lo2(a), ay = hi2(a);
            float t0 = tanhf(cx), t1 = tanhf(cy);
            float s0 = 1.0f / (1.0f + __expf(-ax));
            float s1 = 1.0f / (1.0f + __expf(-ay));
            float hp0 = ep ? hpB0 : hpA0;
            float hp1 = ep ? hpB1 : hpA1;
            float hn0 = fmaf(s0, t0 - hp0, hp0);   // == a*t + (1-a)*hp
            float hn1 = fmaf(s1, t1 - hp1, hp1);
            if (ep == 0) {
                hpA0 = hn0; hpA1 = hn1;
                *(float2*)&g_h0T[s & 1][eC][eb] = make_float2(hn0, hn1);
            } else {
                hpB0 = hn0; hpB1 = hn1;
                *(float2*)&g_h1T[t & 1][eC][eb] = make_float2(hn0, hn1);
                out[((size_t)eb * Tn + t) * Hn + eC]       = hn0;
                out[((size_t)(eb + 1) * Tn + t) * Hn + eC] = hn1;
            }
        }
        grid_barrier(GCTA * bar); bar++;
    }

    // ---- h_final: [2][B][H] appended after outputs ----
    {
        int l = tid >> 7, r = tid & 127;
        int c = r >> 4, bi = r & 15;
        int C = col0 + c, b = b0g + bi;
        const float* src = l ? &g_h1T[(Tn - 1) & 1][0][0] : &g_h0T[(Tn - 1) & 1][0][0];
        out[(size_t)Bn * Tn * Hn + (size_t)l * Bn * Hn + (size_t)b * Hn + C] = src[C * Bn + b];
    }
}

// ---------------- launch ----------------
extern "C" void kernel_launch(void* const* d_in, const int* in_sizes, int n_in,
                              void* d_out, int out_size) {
    const float* x    = (const float*)d_in[0];
    const float* Wih0 = (const float*)d_in[1];
    const float* Whh0 = (const float*)d_in[2];
    const float* bh0  = (const float*)d_in[3];
    const float* Wax0 = (const float*)d_in[4];
    const float* Wah0 = (const float*)d_in[5];
    const float* ba0  = (const float*)d_in[6];
    const float* Wih1 = (const float*)d_in[7];
    const float* Whh1 = (const float*)d_in[8];
    const float* bh1  = (const float*)d_in[9];
    const float* Wax1 = (const float*)d_in[10];
    const float* Wah1 = (const float*)d_in[11];
    const float* ba1  = (const float*)d_in[12];
    float* out = (float*)d_out;

    const int smem = (KA + KB) * NCOL * (int)sizeof(ulonglong2)
                   + 256 * 8 * (int)sizeof(u64)
                   + 4 * NCOL * (int)sizeof(u64);   // 131328 B
    cudaFuncSetAttribute(rnn_kernel, cudaFuncAttributeMaxDynamicSharedMemorySize, smem);

    prep_kernel<<<Tn, THREADS>>>(x);
    rnn_kernel<<<GCTA, THREADS, smem>>>(
        Wih0, Whh0, bh0, Wax0, Wah0, ba0,
        Wih1, Whh1, bh1, Wax1, Wah1, ba1,
        out);
}

// round 4
// speedup vs baseline: 2.2237x; 1.1051x over previous
#include <cuda_runtime.h>

#define Bn 64
#define Tn 2048
#define In 128
#define Hn 256
#define THREADS 256
#define NCOL 16                 // columns per CTA
#define NBAT 8                  // batches per CTA
#define NCG  (Hn / NCOL)        // 16 col-groups
#define NBG  (Bn / NBAT)        // 8 batch-groups
#define GCTA (NCG * NBG)        // 128 CTAs
#define KA 384
#define KB 512
#define RSTRIDE 10              // red stride (u64) — conflict-free banks

typedef unsigned long long u64;

// ---------------- device scratch (static; no allocations) ----------------
// State stored PRE-DUPLICATED: element b holds {v,v} packed in u64.
__device__ __align__(256) u64 g_xT2[(size_t)Tn * In * Bn];   // [t][k][b], 134MB
__device__ __align__(256) u64 g_h0T2[2 * Hn * Bn];
__device__ __align__(256) u64 g_h1T2[2 * Hn * Bn];
__device__ unsigned g_count;

// ---------------- packed f32x2 helpers ----------------
__device__ __forceinline__ void fma2(u64 &d, u64 a, u64 b) {
    asm("fma.rn.f32x2 %0, %1, %2, %0;" : "+l"(d) : "l"(a), "l"(b));
}
__device__ __forceinline__ u64 add2(u64 a, u64 b) {
    u64 d; asm("add.rn.f32x2 %0, %1, %2;" : "=l"(d) : "l"(a), "l"(b)); return d;
}
__device__ __forceinline__ u64 dup2(float f) {
    u64 d; asm("mov.b64 %0, {%1, %1};" : "=l"(d) : "f"(f)); return d;
}
__device__ __forceinline__ u64 pack2(float lo, float hi) {
    u64 d; asm("mov.b64 %0, {%1, %2};" : "=l"(d) : "f"(lo), "f"(hi)); return d;
}
__device__ __forceinline__ float lo2(u64 v) { return __uint_as_float((unsigned)(v & 0xffffffffull)); }
__device__ __forceinline__ float hi2(u64 v) { return __uint_as_float((unsigned)(v >> 32)); }

// L2-coherent 16B load / 8B store (state is produced by other SMs each step)
__device__ __forceinline__ void ldcg2(const u64* p, u64 &a, u64 &b) {
    asm volatile("ld.global.cg.v2.u64 {%0, %1}, [%2];" : "=l"(a), "=l"(b) : "l"(p));
}
__device__ __forceinline__ void stcg(u64* p, u64 v) {
    asm volatile("st.global.cg.b64 [%0], %1;" :: "l"(p), "l"(v) : "memory");
}

// ---------------- grid barrier ----------------
__device__ __forceinline__ void grid_barrier(unsigned target) {
    __syncthreads();
    if (threadIdx.x == 0) {
        __threadfence();
        atomicAdd(&g_count, 1u);
        while (*((volatile unsigned*)&g_count) < target) { }
        __threadfence();
    }
    __syncthreads();
}

// ---------------- prep: transpose + dup x, zero states, reset barrier ----------------
__global__ void prep_kernel(const float* __restrict__ x) {
    __shared__ float s[In][65];
    const int t = blockIdx.x;
    const int tid = threadIdx.x;
    for (int idx = tid; idx < Bn * In; idx += THREADS) {
        int b = idx >> 7, i = idx & (In - 1);
        s[i][b] = x[((size_t)b * Tn + t) * In + i];
    }
    __syncthreads();
    for (int idx = tid; idx < In * Bn; idx += THREADS) {
        int i = idx >> 6, b = idx & (Bn - 1);
        g_xT2[((size_t)t * In + i) * Bn + b] = dup2(s[i][b]);
    }
    if (t == 0 && tid == 0) g_count = 0u;
    if (t < 4) {
        u64* z = (t < 2) ? (g_h0T2 + (size_t)t * Hn * Bn) : (g_h1T2 + (size_t)(t - 2) * Hn * Bn);
        for (int i = tid; i < Hn * Bn; i += THREADS) z[i] = 0ull;
    }
}

// ---------------- persistent RNN kernel ----------------
__global__ void __launch_bounds__(THREADS, 1) rnn_kernel(
    const float* __restrict__ Wih0, const float* __restrict__ Whh0,
    const float* __restrict__ bh0,  const float* __restrict__ Wax0,
    const float* __restrict__ Wah0, const float* __restrict__ ba0,
    const float* __restrict__ Wih1, const float* __restrict__ Whh1,
    const float* __restrict__ bh1,  const float* __restrict__ Wax1,
    const float* __restrict__ Wah1, const float* __restrict__ ba1,
    float* __restrict__ out)
{
    extern __shared__ u64 sm[];
    u64* wAs   = sm;                       // [KA][16] (wc,wa) pairs
    u64* wBs   = wAs + KA * NCOL;          // [KB][16]
    u64* red   = wBs + KB * NCOL;          // [256][RSTRIDE]
    u64* sbias = red + THREADS * RSTRIDE;  // [2][16]

    const int tid  = threadIdx.x;
    const int cg   = blockIdx.x & (NCG - 1);
    const int bg   = blockIdx.x >> 4;
    const int col0 = cg * NCOL;
    const int b0g  = bg * NBAT;

    // ---- one-time weight gather: (wc, wa) packed per col per k ----
    for (int idx = tid; idx < KA * NCOL; idx += THREADS) {
        int k = idx >> 4, c = idx & 15, C = col0 + c;
        float wc = (k < In) ? Wih0[k * Hn + C] : Whh0[(k - In) * Hn + C];
        float wa = (k < In) ? Wax0[k * Hn + C] : Wah0[(k - In) * Hn + C];
        wAs[idx] = pack2(wc, wa);
    }
    for (int idx = tid; idx < KB * NCOL; idx += THREADS) {
        int k = idx >> 4, c = idx & 15, C = col0 + c;
        float wc = (k < Hn) ? Wih1[k * Hn + C] : Whh1[(k - Hn) * Hn + C];
        float wa = (k < Hn) ? Wax1[k * Hn + C] : Wah1[(k - Hn) * Hn + C];
        wBs[idx] = pack2(wc, wa);
    }
    if (tid < 2 * NCOL) {
        int c = tid & 15, l = tid >> 4;
        sbias[tid] = l ? pack2(bh1[col0 + c], ba1[col0 + c])
                       : pack2(bh0[col0 + c], ba0[col0 + c]);
    }
    __syncthreads();

    // ---- accumulation mapping: warp = K-slice; lane = (batch-pair, col-pair) ----
    const int w  = tid >> 5;
    const int ln = tid & 31;
    const int bp = ln >> 3;            // 0..3  batch-pair
    const int cp = ln & 7;             // 0..7  col-pair
    const int b0 = b0g + bp * 2;       // even

    // ---- epilogue mapping: thread -> (phase, batch, col) cell ----
    const int rp   = tid >> 7;
    const int cell = tid & 127;
    const int rb   = cell >> 4;        // 0..7
    const int rc   = cell & 15;        // 0..15
    const int ridx = (rb >> 1) * 8 + (rc >> 1);            // staging lane
    const int raid = rp * 4 + (rb & 1) * 2 + (rc & 1);     // staging acc slot
    float hprev = 0.0f;

    unsigned bar = 1;

    // iteration t: phase B -> h1[t] (t>=0); phase A -> h0[t+1] (t+1<Tn)
    for (int t = -1; t < Tn; t++) {
        const int s = t + 1;
        const bool doA = (s < Tn);
        const bool doB = (t >= 0);

        u64 aA00 = 0, aA01 = 0, aA10 = 0, aA11 = 0;   // [batch][col] gate-packed
        u64 aB00 = 0, aB01 = 0, aB10 = 0, aB11 = 0;

        // -- x-part (A): K-slice of 16 --
        if (doA) {
            const u64* xp = g_xT2 + ((size_t)s * In + w * 16) * Bn + b0;
            const u64* wp = wAs + (w * 16) * NCOL + cp * 2;
#pragma unroll
            for (int k = 0; k < 16; k++) {
                u64 s0, s1; ldcg2(xp + (size_t)k * Bn, s0, s1);
                ulonglong2 wv = *(const ulonglong2*)(wp + k * NCOL);
                fma2(aA00, s0, wv.x); fma2(aA01, s0, wv.y);
                fma2(aA10, s1, wv.x); fma2(aA11, s1, wv.y);
            }
        }

        // -- shared h0[t] part: feeds A (Whh0/Wah0) and B (Wih1/Wax1) --
        {
            const u64* hp  = g_h0T2 + ((size_t)(t & 1) * Hn + w * 32) * Bn + b0;
            const u64* wpa = wAs + (In + w * 32) * NCOL + cp * 2;
            const u64* wpb = wBs + (w * 32) * NCOL + cp * 2;
            if (doA && doB) {
#pragma unroll 8
                for (int k = 0; k < 32; k++) {
                    u64 s0, s1; ldcg2(hp + (size_t)k * Bn, s0, s1);
                    ulonglong2 wa = *(const ulonglong2*)(wpa + k * NCOL);
                    ulonglong2 wb = *(const ulonglong2*)(wpb + k * NCOL);
                    fma2(aA00, s0, wa.x); fma2(aA01, s0, wa.y);
                    fma2(aA10, s1, wa.x); fma2(aA11, s1, wa.y);
                    fma2(aB00, s0, wb.x); fma2(aB01, s0, wb.y);
                    fma2(aB10, s1, wb.x); fma2(aB11, s1, wb.y);
                }
            } else if (doA) {
#pragma unroll 8
                for (int k = 0; k < 32; k++) {
                    u64 s0, s1; ldcg2(hp + (size_t)k * Bn, s0, s1);
                    ulonglong2 wa = *(const ulonglong2*)(wpa + k * NCOL);
                    fma2(aA00, s0, wa.x); fma2(aA01, s0, wa.y);
                    fma2(aA10, s1, wa.x); fma2(aA11, s1, wa.y);
                }
            } else {
#pragma unroll 8
                for (int k = 0; k < 32; k++) {
                    u64 s0, s1; ldcg2(hp + (size_t)k * Bn, s0, s1);
                    ulonglong2 wb = *(const ulonglong2*)(wpb + k * NCOL);
                    fma2(aB00, s0, wb.x); fma2(aB01, s0, wb.y);
                    fma2(aB10, s1, wb.x); fma2(aB11, s1, wb.y);
                }
            }
        }

        // -- h1[t-1] part (B): K-slice of 32 --
        if (doB) {
            const u64* hp = g_h1T2 + ((size_t)((t + 1) & 1) * Hn + w * 32) * Bn + b0;
            const u64* wp = wBs + (Hn + w * 32) * NCOL + cp * 2;
#pragma unroll 8
            for (int k = 0; k < 32; k++) {
                u64 s0, s1; ldcg2(hp + (size_t)k * Bn, s0, s1);
                ulonglong2 wv = *(const ulonglong2*)(wp + k * NCOL);
                fma2(aB00, s0, wv.x); fma2(aB01, s0, wv.y);
                fma2(aB10, s1, wv.x); fma2(aB11, s1, wv.y);
            }
        }

        // -- stage partials --
        {
            u64* rr = red + tid * RSTRIDE;
            *(ulonglong2*)(rr + 0) = make_ulonglong2(aA00, aA01);
            *(ulonglong2*)(rr + 2) = make_ulonglong2(aA10, aA11);
            *(ulonglong2*)(rr + 4) = make_ulonglong2(aB00, aB01);
            *(ulonglong2*)(rr + 6) = make_ulonglong2(aB10, aB11);
        }
        __syncthreads();

        // -- reduce over 8 warps + epilogue (1 cell per thread) --
        if (rp ? doB : doA) {
            u64 acc = sbias[rp * NCOL + rc];
#pragma unroll
            for (int ww = 0; ww < 8; ww++)
                acc = add2(acc, red[(ww * 32 + ridx) * RSTRIDE + raid]);
            float cnd = lo2(acc), alp = hi2(acc);
            float tv = tanhf(cnd);
            float sg = 1.0f / (1.0f + __expf(-alp));
            float hn = fmaf(sg, tv - hprev, hprev);
            hprev = hn;
            u64 hd = dup2(hn);
            const int C = col0 + rc, B = b0g + rb;
            if (rp == 0) {
                stcg(g_h0T2 + ((size_t)(s & 1) * Hn + C) * Bn + B, hd);
            } else {
                stcg(g_h1T2 + ((size_t)(t & 1) * Hn + C) * Bn + B, hd);
                out[((size_t)B * Tn + t) * Hn + C] = hn;
            }
        }
        grid_barrier(GCTA * bar); bar++;
    }

    // ---- h_final: [2][B][H] appended after outputs ----
    {
        const int l = tid >> 7, r = tid & 127;
        const int b = r >> 4, c = r & 15;
        const int C = col0 + c, B = b0g + b;
        const u64* src = l ? (g_h1T2 + ((size_t)1 * Hn + C) * Bn + B)
                           : (g_h0T2 + ((size_t)1 * Hn + C) * Bn + B);  // (Tn-1)&1 == 1
        out[(size_t)Bn * Tn * Hn + (size_t)l * Bn * Hn + (size_t)B * Hn + C] = lo2(*src);
    }
}

// ---------------- launch ----------------
extern "C" void kernel_launch(void* const* d_in, const int* in_sizes, int n_in,
                              void* d_out, int out_size) {
    const float* x    = (const float*)d_in[0];
    const float* Wih0 = (const float*)d_in[1];
    const float* Whh0 = (const float*)d_in[2];
    const float* bh0  = (const float*)d_in[3];
    const float* Wax0 = (const float*)d_in[4];
    const float* Wah0 = (const float*)d_in[5];
    const float* ba0  = (const float*)d_in[6];
    const float* Wih1 = (const float*)d_in[7];
    const float* Whh1 = (const float*)d_in[8];
    const float* bh1  = (const float*)d_in[9];
    const float* Wax1 = (const float*)d_in[10];
    const float* Wah1 = (const float*)d_in[11];
    const float* ba1  = (const float*)d_in[12];
    float* out = (float*)d_out;

    const int smem = (KA + KB) * NCOL * 8 + THREADS * RSTRIDE * 8 + 2 * NCOL * 8;
    cudaFuncSetAttribute(rnn_kernel, cudaFuncAttributeMaxDynamicSharedMemorySize, smem);

    prep_kernel<<<Tn, THREADS>>>(x);
    rnn_kernel<<<GCTA, THREADS, smem>>>(
        Wih0, Whh0, bh0, Wax0, Wah0, ba0,
        Wih1, Whh1, bh1, Wax1, Wah1, ba1,
        out);
}

// round 5
// speedup vs baseline: 2.3167x; 1.0418x over previous
#include <cuda_runtime.h>

#define Bn 64
#define Tn 2048
#define In 128
#define Hn 256
#define THREADS 512
#define PT 256                  // prep kernel threads
#define NCOL 16                 // columns per CTA
#define NBAT 8                  // batches per CTA
#define NCG  (Hn / NCOL)        // 16 col-groups
#define NBG  (Bn / NBAT)        // 8 batch-groups
#define GCTA (NCG * NBG)        // 128 CTAs
#define KA 384
#define KB 512
#define RSTRIDE 10              // staging stride (u64), bank-skewed

typedef unsigned long long u64;

// ---------------- device scratch (static; no allocations) ----------------
// State stored PRE-DUPLICATED: element b holds {v,v} packed in u64.
__device__ __align__(256) u64 g_xT2[(size_t)Tn * In * Bn];
__device__ __align__(256) u64 g_h0T2[2 * Hn * Bn];
__device__ __align__(256) u64 g_h1T2[2 * Hn * Bn];
__device__ unsigned g_count;

// ---------------- packed f32x2 helpers ----------------
__device__ __forceinline__ void fma2(u64 &d, u64 a, u64 b) {
    asm("fma.rn.f32x2 %0, %1, %2, %0;" : "+l"(d) : "l"(a), "l"(b));
}
__device__ __forceinline__ u64 add2(u64 a, u64 b) {
    u64 d; asm("add.rn.f32x2 %0, %1, %2;" : "=l"(d) : "l"(a), "l"(b)); return d;
}
__device__ __forceinline__ u64 dup2(float f) {
    u64 d; asm("mov.b64 %0, {%1, %1};" : "=l"(d) : "f"(f)); return d;
}
__device__ __forceinline__ u64 pack2(float lo, float hi) {
    u64 d; asm("mov.b64 %0, {%1, %2};" : "=l"(d) : "f"(lo), "f"(hi)); return d;
}
__device__ __forceinline__ float lo2(u64 v) { return __uint_as_float((unsigned)(v & 0xffffffffull)); }
__device__ __forceinline__ float hi2(u64 v) { return __uint_as_float((unsigned)(v >> 32)); }

// L2-coherent load/store (state is produced by other SMs each step)
__device__ __forceinline__ void ldcg2(const u64* p, u64 &a, u64 &b) {
    asm volatile("ld.global.cg.v2.u64 {%0, %1}, [%2];" : "=l"(a), "=l"(b) : "l"(p));
}
__device__ __forceinline__ void stcg(u64* p, u64 v) {
    asm volatile("st.global.cg.b64 [%0], %1;" :: "l"(p), "l"(v) : "memory");
}

// ---------------- grid barrier ----------------
__device__ __forceinline__ void grid_barrier(unsigned target) {
    __syncthreads();
    if (threadIdx.x == 0) {
        __threadfence();
        atomicAdd(&g_count, 1u);
        while (*((volatile unsigned*)&g_count) < target) { }
        __threadfence();
    }
    __syncthreads();
}

// ---------------- prep: transpose + dup x, zero states, reset barrier ----------------
__global__ void prep_kernel(const float* __restrict__ x) {
    __shared__ float s[In][65];
    const int t = blockIdx.x;
    const int tid = threadIdx.x;
    for (int idx = tid; idx < Bn * In; idx += PT) {
        int b = idx >> 7, i = idx & (In - 1);
        s[i][b] = x[((size_t)b * Tn + t) * In + i];
    }
    __syncthreads();
    for (int idx = tid; idx < In * Bn; idx += PT) {
        int i = idx >> 6, b = idx & (Bn - 1);
        g_xT2[((size_t)t * In + i) * Bn + b] = dup2(s[i][b]);
    }
    if (t == 0 && tid == 0) g_count = 0u;
    if (t < 4) {
        u64* z = (t < 2) ? (g_h0T2 + (size_t)t * Hn * Bn) : (g_h1T2 + (size_t)(t - 2) * Hn * Bn);
        for (int i = tid; i < Hn * Bn; i += PT) z[i] = 0ull;
    }
}

// ---------------- persistent RNN kernel ----------------
__global__ void __launch_bounds__(THREADS, 1) rnn_kernel(
    const float* __restrict__ Wih0, const float* __restrict__ Whh0,
    const float* __restrict__ bh0,  const float* __restrict__ Wax0,
    const float* __restrict__ Wah0, const float* __restrict__ ba0,
    const float* __restrict__ Wih1, const float* __restrict__ Whh1,
    const float* __restrict__ bh1,  const float* __restrict__ Wax1,
    const float* __restrict__ Wah1, const float* __restrict__ ba1,
    float* __restrict__ out)
{
    extern __shared__ u64 sm[];
    u64* wAs   = sm;                       // [KA][16] (wc,wa) pairs
    u64* wBs   = wAs + KA * NCOL;          // [KB][16]
    u64* red   = wBs + KB * NCOL;          // [512][RSTRIDE]
    u64* sbias = red + THREADS * RSTRIDE;  // [2][16]

    const int tid  = threadIdx.x;
    const int cg   = blockIdx.x & (NCG - 1);
    const int bg   = blockIdx.x >> 4;
    const int col0 = cg * NCOL;
    const int b0g  = bg * NBAT;

    // ---- one-time weight gather: (wc, wa) packed per col per k ----
    for (int idx = tid; idx < KA * NCOL; idx += THREADS) {
        int k = idx >> 4, c = idx & 15, C = col0 + c;
        float wc = (k < In) ? Wih0[k * Hn + C] : Whh0[(k - In) * Hn + C];
        float wa = (k < In) ? Wax0[k * Hn + C] : Wah0[(k - In) * Hn + C];
        wAs[idx] = pack2(wc, wa);
    }
    for (int idx = tid; idx < KB * NCOL; idx += THREADS) {
        int k = idx >> 4, c = idx & 15, C = col0 + c;
        float wc = (k < Hn) ? Wih1[k * Hn + C] : Whh1[(k - Hn) * Hn + C];
        float wa = (k < Hn) ? Wax1[k * Hn + C] : Wah1[(k - Hn) * Hn + C];
        wBs[idx] = pack2(wc, wa);
    }
    if (tid < 2 * NCOL) {
        int c = tid & 15, l = tid >> 4;
        sbias[tid] = l ? pack2(bh1[col0 + c], ba1[col0 + c])
                       : pack2(bh0[col0 + c], ba0[col0 + c]);
    }
    __syncthreads();

    // ---- accumulation mapping: 16 warps = K-slices; lane = (batch-pair, col-pair) ----
    const int w  = tid >> 5;           // 0..15
    const int ln = tid & 31;
    const int bp = ln >> 3;            // 0..3  batch-pair
    const int cp = ln & 7;             // 0..7  col-pair
    const int b0 = b0g + bp * 2;
    const int kx = w * 8;              // x slice (128/16)
    const int kh = w * 16;             // shared h0 + h1 slice (256/16)

    // ---- epilogue mapping (tid < 256): (phase, batch, col) cell ----
    const int rp   = tid >> 7;
    const int cell = tid & 127;
    const int rb   = cell >> 4;        // 0..7
    const int rc   = cell & 15;        // 0..15
    const int ridx = (rb >> 1) * 8 + (rc >> 1);            // staging lane
    const int raid = rp * 4 + (rb & 1) * 2 + (rc & 1);     // staging acc slot
    float hprev = 0.0f;

    // x-part prefetch helper (no barrier dependence)
    auto xpart = [&](int s, u64 &a00, u64 &a01, u64 &a10, u64 &a11) {
        const u64* xp = g_xT2 + ((size_t)s * In + kx) * Bn + b0;
        const u64* wp = wAs + kx * NCOL + cp * 2;
#pragma unroll
        for (int k = 0; k < 8; k++) {
            u64 s0, s1; ldcg2(xp + (size_t)k * Bn, s0, s1);
            ulonglong2 wv = *(const ulonglong2*)(wp + k * NCOL);
            fma2(a00, s0, wv.x); fma2(a01, s0, wv.y);
            fma2(a10, s1, wv.x); fma2(a11, s1, wv.y);
        }
    };

    u64 x00 = 0, x01 = 0, x10 = 0, x11 = 0;
    xpart(0, x00, x01, x10, x11);

    unsigned bar = 1;

    // iteration t: phase B -> h1[t] (t>=0); phase A -> h0[t+1] (t+1<Tn)
    for (int t = -1; t < Tn; t++) {
        const int s = t + 1;
        const bool doA = (s < Tn);
        const bool doB = (t >= 0);

        u64 aA00 = x00, aA01 = x01, aA10 = x10, aA11 = x11;
        u64 aB00 = 0, aB01 = 0, aB10 = 0, aB11 = 0;

        // -- shared h0[t] part: feeds A (Whh0/Wah0) and B (Wih1/Wax1) --
        {
            const u64* hp  = g_h0T2 + ((size_t)(t & 1) * Hn + kh) * Bn + b0;
            const u64* wpa = wAs + (In + kh) * NCOL + cp * 2;
            const u64* wpb = wBs + kh * NCOL + cp * 2;
            if (doA && doB) {
#pragma unroll 8
                for (int k = 0; k < 16; k++) {
                    u64 s0, s1; ldcg2(hp + (size_t)k * Bn, s0, s1);
                    ulonglong2 wa = *(const ulonglong2*)(wpa + k * NCOL);
                    ulonglong2 wb = *(const ulonglong2*)(wpb + k * NCOL);
                    fma2(aA00, s0, wa.x); fma2(aA01, s0, wa.y);
                    fma2(aA10, s1, wa.x); fma2(aA11, s1, wa.y);
                    fma2(aB00, s0, wb.x); fma2(aB01, s0, wb.y);
                    fma2(aB10, s1, wb.x); fma2(aB11, s1, wb.y);
                }
            } else if (doA) {
#pragma unroll 8
                for (int k = 0; k < 16; k++) {
                    u64 s0, s1; ldcg2(hp + (size_t)k * Bn, s0, s1);
                    ulonglong2 wa = *(const ulonglong2*)(wpa + k * NCOL);
                    fma2(aA00, s0, wa.x); fma2(aA01, s0, wa.y);
                    fma2(aA10, s1, wa.x); fma2(aA11, s1, wa.y);
                }
            } else {
#pragma unroll 8
                for (int k = 0; k < 16; k++) {
                    u64 s0, s1; ldcg2(hp + (size_t)k * Bn, s0, s1);
                    ulonglong2 wb = *(const ulonglong2*)(wpb + k * NCOL);
                    fma2(aB00, s0, wb.x); fma2(aB01, s0, wb.y);
                    fma2(aB10, s1, wb.x); fma2(aB11, s1, wb.y);
                }
            }
        }

        // -- h1[t-1] part (B) --
        if (doB) {
            const u64* hp = g_h1T2 + ((size_t)((t + 1) & 1) * Hn + kh) * Bn + b0;
            const u64* wp = wBs + (Hn + kh) * NCOL + cp * 2;
#pragma unroll 8
            for (int k = 0; k < 16; k++) {
                u64 s0, s1; ldcg2(hp + (size_t)k * Bn, s0, s1);
                ulonglong2 wv = *(const ulonglong2*)(wp + k * NCOL);
                fma2(aB00, s0, wv.x); fma2(aB01, s0, wv.y);
                fma2(aB10, s1, wv.x); fma2(aB11, s1, wv.y);
            }
        }

        // -- stage partials --
        {
            u64* rr = red + tid * RSTRIDE;
            *(ulonglong2*)(rr + 0) = make_ulonglong2(aA00, aA01);
            *(ulonglong2*)(rr + 2) = make_ulonglong2(aA10, aA11);
            *(ulonglong2*)(rr + 4) = make_ulonglong2(aB00, aB01);
            *(ulonglong2*)(rr + 6) = make_ulonglong2(aB10, aB11);
        }
        __syncthreads();

        // -- reduce over 16 warps + epilogue (tid<256); others prefetch x --
        if (tid < 256 && (rp ? doB : doA)) {
            u64 acc0 = sbias[rp * NCOL + rc];
            u64 acc1 = 0;
#pragma unroll
            for (int ww = 0; ww < 16; ww += 2) {
                acc0 = add2(acc0, red[(ww * 32 + ridx) * RSTRIDE + raid]);
                acc1 = add2(acc1, red[((ww + 1) * 32 + ridx) * RSTRIDE + raid]);
            }
            u64 acc = add2(acc0, acc1);
            float cnd = lo2(acc), alp = hi2(acc);
            // fast tanh / sigmoid via __expf + __fdividef (~1e-7 rel err)
            float tv = 1.0f - __fdividef(2.0f, __expf(2.0f * cnd) + 1.0f);
            float sg = __fdividef(1.0f, 1.0f + __expf(-alp));
            float hn = fmaf(sg, tv - hprev, hprev);
            hprev = hn;
            u64 hd = dup2(hn);
            const int C = col0 + rc, B = b0g + rb;
            if (rp == 0) {
                stcg(g_h0T2 + ((size_t)(s & 1) * Hn + C) * Bn + B, hd);
            } else {
                stcg(g_h1T2 + ((size_t)(t & 1) * Hn + C) * Bn + B, hd);
                out[((size_t)B * Tn + t) * Hn + C] = hn;
            }
        }

        // -- prefetch x-part for step t+2 (fills the barrier window) --
        x00 = 0; x01 = 0; x10 = 0; x11 = 0;
        if (t + 2 < Tn) xpart(t + 2, x00, x01, x10, x11);

        grid_barrier(GCTA * bar); bar++;
    }

    // ---- h_final: [2][B][H] appended after outputs ----
    if (tid < 256) {
        const int l = tid >> 7, r = tid & 127;
        const int b = r >> 4, c = r & 15;
        const int C = col0 + c, B = b0g + b;
        const u64* src = l ? (g_h1T2 + ((size_t)1 * Hn + C) * Bn + B)
                           : (g_h0T2 + ((size_t)1 * Hn + C) * Bn + B);  // (Tn-1)&1 == 1
        out[(size_t)Bn * Tn * Hn + (size_t)l * Bn * Hn + (size_t)B * Hn + C] = lo2(*src);
    }
}

// ---------------- launch ----------------
extern "C" void kernel_launch(void* const* d_in, const int* in_sizes, int n_in,
                              void* d_out, int out_size) {
    const float* x    = (const float*)d_in[0];
    const float* Wih0 = (const float*)d_in[1];
    const float* Whh0 = (const float*)d_in[2];
    const float* bh0  = (const float*)d_in[3];
    const float* Wax0 = (const float*)d_in[4];
    const float* Wah0 = (const float*)d_in[5];
    const float* ba0  = (const float*)d_in[6];
    const float* Wih1 = (const float*)d_in[7];
    const float* Whh1 = (const float*)d_in[8];
    const float* bh1  = (const float*)d_in[9];
    const float* Wax1 = (const float*)d_in[10];
    const float* Wah1 = (const float*)d_in[11];
    const float* ba1  = (const float*)d_in[12];
    float* out = (float*)d_out;

    const int smem = (KA + KB) * NCOL * 8 + THREADS * RSTRIDE * 8 + 2 * NCOL * 8;
    cudaFuncSetAttribute(rnn_kernel, cudaFuncAttributeMaxDynamicSharedMemorySize, smem);

    prep_kernel<<<Tn, PT>>>(x);
    rnn_kernel<<<GCTA, THREADS, smem>>>(
        Wih0, Whh0, bh0, Wax0, Wah0, ba0,
        Wih1, Whh1, bh1, Wax1, Wah1, ba1,
        out);
}

// round 6
// speedup vs baseline: 2.4188x; 1.0441x over previous
#include <cuda_runtime.h>

#define Bn 64
#define Tn 2048
#define In 128
#define Hn 256
#define THREADS 512
#define PT 256
#define NCOL 16                 // columns per CTA
#define NBAT 8                  // batches per CTA
#define NCG  (Hn / NCOL)        // 16 col-groups
#define NBG  (Bn / NBAT)        // 8 batch-groups
#define GCTA (NCG * NBG)        // 128 CTAs
#define KA 384
#define KB 512
#define RSTRIDE 10

typedef unsigned long long u64;

// ---------------- device scratch (static; no allocations) ----------------
__device__ __align__(256) u64   g_xT2[(size_t)Tn * In * Bn];  // x dup'd {v,v}: [t][k][b]
__device__ __align__(256) float g_h0[2 * Hn * Bn];            // plain fp32, [buf][k][b]
__device__ __align__(256) float g_h1[2 * Hn * Bn];
__device__ unsigned g_count;

// ---------------- packed f32x2 helpers ----------------
__device__ __forceinline__ void fma2(u64 &d, u64 a, u64 b) {
    asm("fma.rn.f32x2 %0, %1, %2, %0;" : "+l"(d) : "l"(a), "l"(b));
}
__device__ __forceinline__ u64 add2(u64 a, u64 b) {
    u64 d; asm("add.rn.f32x2 %0, %1, %2;" : "=l"(d) : "l"(a), "l"(b)); return d;
}
__device__ __forceinline__ u64 dup2(float f) {
    u64 d; asm("mov.b64 %0, {%1, %1};" : "=l"(d) : "f"(f)); return d;
}
__device__ __forceinline__ u64 pack2(float lo, float hi) {
    u64 d; asm("mov.b64 %0, {%1, %2};" : "=l"(d) : "f"(lo), "f"(hi)); return d;
}
__device__ __forceinline__ float lo2(u64 v) { return __uint_as_float((unsigned)(v & 0xffffffffull)); }
__device__ __forceinline__ float hi2(u64 v) { return __uint_as_float((unsigned)(v >> 32)); }

// L2-coherent accesses (state crosses SMs every step)
__device__ __forceinline__ void ldcg2(const u64* p, u64 &a, u64 &b) {
    asm volatile("ld.global.cg.v2.u64 {%0, %1}, [%2];" : "=l"(a), "=l"(b) : "l"(p));
}
__device__ __forceinline__ float4 ldcgf4(const float* p) {
    float4 v;
    asm volatile("ld.global.cg.v4.f32 {%0, %1, %2, %3}, [%4];"
                 : "=f"(v.x), "=f"(v.y), "=f"(v.z), "=f"(v.w) : "l"(p));
    return v;
}
__device__ __forceinline__ void stcgf(float* p, float v) {
    asm volatile("st.global.cg.f32 [%0], %1;" :: "l"(p), "f"(v) : "memory");
}

// ---------------- grid barrier (release/acquire, no membar) ----------------
__device__ __forceinline__ void grid_barrier(unsigned target) {
    __syncthreads();
    if (threadIdx.x == 0) {
        unsigned old;
        asm volatile("atom.release.gpu.global.add.u32 %0, [%1], 1;"
                     : "=r"(old) : "l"(&g_count) : "memory");
        unsigned v;
        do {
            asm volatile("ld.acquire.gpu.global.u32 %0, [%1];"
                         : "=r"(v) : "l"(&g_count) : "memory");
        } while (v < target);
    }
    __syncthreads();
}

// ---------------- prep: transpose + dup x, zero states, reset barrier ----------------
__global__ void prep_kernel(const float* __restrict__ x) {
    __shared__ float s[In][65];
    const int t = blockIdx.x;
    const int tid = threadIdx.x;
    for (int idx = tid; idx < Bn * In; idx += PT) {
        int b = idx >> 7, i = idx & (In - 1);
        s[i][b] = x[((size_t)b * Tn + t) * In + i];
    }
    __syncthreads();
    for (int idx = tid; idx < In * Bn; idx += PT) {
        int i = idx >> 6, b = idx & (Bn - 1);
        g_xT2[((size_t)t * In + i) * Bn + b] = dup2(s[i][b]);
    }
    if (t == 0 && tid == 0) g_count = 0u;
    if (t < 2) {
        for (int i = tid; i < Hn * Bn; i += PT) {
            g_h0[t * Hn * Bn + i] = 0.0f;
            g_h1[t * Hn * Bn + i] = 0.0f;
        }
    }
}

// ---------------- persistent RNN kernel ----------------
__global__ void __launch_bounds__(THREADS, 1) rnn_kernel(
    const float* __restrict__ Wih0, const float* __restrict__ Whh0,
    const float* __restrict__ bh0,  const float* __restrict__ Wax0,
    const float* __restrict__ Wah0, const float* __restrict__ ba0,
    const float* __restrict__ Wih1, const float* __restrict__ Whh1,
    const float* __restrict__ bh1,  const float* __restrict__ Wax1,
    const float* __restrict__ Wah1, const float* __restrict__ ba1,
    float* __restrict__ out)
{
    extern __shared__ u64 sm[];
    u64* wAs   = sm;                        // [KA][16] (wc,wa) pairs
    u64* wBs   = wAs + KA * NCOL;           // [KB][16]
    u64* sh0   = wBs + KB * NCOL;           // [Hn][NBAT] dup'd state h0[t]
    u64* sh1   = sh0 + Hn * NBAT;           // [Hn][NBAT] dup'd state h1[t-1]
    u64* red   = sh1 + Hn * NBAT;           // [512][RSTRIDE]
    u64* sbias = red + THREADS * RSTRIDE;   // [2][16]

    const int tid  = threadIdx.x;
    const int cg   = blockIdx.x & (NCG - 1);
    const int bg   = blockIdx.x >> 4;
    const int col0 = cg * NCOL;
    const int b0g  = bg * NBAT;

    // ---- one-time weight gather: (wc, wa) packed per col per k ----
    for (int idx = tid; idx < KA * NCOL; idx += THREADS) {
        int k = idx >> 4, c = idx & 15, C = col0 + c;
        float wc = (k < In) ? Wih0[k * Hn + C] : Whh0[(k - In) * Hn + C];
        float wa = (k < In) ? Wax0[k * Hn + C] : Wah0[(k - In) * Hn + C];
        wAs[idx] = pack2(wc, wa);
    }
    for (int idx = tid; idx < KB * NCOL; idx += THREADS) {
        int k = idx >> 4, c = idx & 15, C = col0 + c;
        float wc = (k < Hn) ? Wih1[k * Hn + C] : Whh1[(k - Hn) * Hn + C];
        float wa = (k < Hn) ? Wax1[k * Hn + C] : Wah1[(k - Hn) * Hn + C];
        wBs[idx] = pack2(wc, wa);
    }
    if (tid < 2 * NCOL) {
        int c = tid & 15, l = tid >> 4;
        sbias[tid] = l ? pack2(bh1[col0 + c], ba1[col0 + c])
                       : pack2(bh0[col0 + c], ba0[col0 + c]);
    }
    __syncthreads();

    // ---- accumulation mapping: 16 warps = K-slices; lane = (batch-pair, col-pair) ----
    const int w  = tid >> 5;
    const int ln = tid & 31;
    const int bp = ln >> 3;
    const int cp = ln & 7;
    const int b0 = b0g + bp * 2;
    const int kx = w * 8;
    const int kh = w * 16;

    // ---- staging mapping: thread -> (k, batch-half) float4 ----
    const int sk = tid >> 1;
    const int sb = (tid & 1) * 4;

    // ---- epilogue mapping (tid < 256) ----
    const int rp   = tid >> 7;
    const int cell = tid & 127;
    const int rb   = cell >> 4;
    const int rc   = cell & 15;
    const int ridx = (rb >> 1) * 8 + (rc >> 1);
    const int raid = rp * 4 + (rb & 1) * 2 + (rc & 1);
    float hprev = 0.0f;

    // x-part prefetch (no barrier dependence)
    auto xpart = [&](int s, u64 &a00, u64 &a01, u64 &a10, u64 &a11) {
        const u64* xp = g_xT2 + ((size_t)s * In + kx) * Bn + b0;
        const u64* wp = wAs + kx * NCOL + cp * 2;
#pragma unroll
        for (int k = 0; k < 8; k++) {
            u64 s0, s1; ldcg2(xp + (size_t)k * Bn, s0, s1);
            ulonglong2 wv = *(const ulonglong2*)(wp + k * NCOL);
            fma2(a00, s0, wv.x); fma2(a01, s0, wv.y);
            fma2(a10, s1, wv.x); fma2(a11, s1, wv.y);
        }
    };

    u64 x00 = 0, x01 = 0, x10 = 0, x11 = 0;
    xpart(0, x00, x01, x10, x11);

    unsigned bar = 1;

    // iteration t: phase B -> h1[t] (t>=0); phase A -> h0[t+1] (t+1<Tn)
    for (int t = -1; t < Tn; t++) {
        const int s = t + 1;
        const bool doA = (s < Tn);
        const bool doB = (t >= 0);

        // -- stage h0[t], h1[t-1] into SMEM (coalesced, dedup'd source) --
        {
            float4 v0 = ldcgf4(&g_h0[((t & 1) * Hn + sk) * Bn + b0g + sb]);
            float4 v1 = ldcgf4(&g_h1[((((t + 1) & 1)) * Hn + sk) * Bn + b0g + sb]);
            u64* d0 = sh0 + sk * NBAT + sb;
            u64* d1 = sh1 + sk * NBAT + sb;
            d0[0] = dup2(v0.x); d0[1] = dup2(v0.y); d0[2] = dup2(v0.z); d0[3] = dup2(v0.w);
            d1[0] = dup2(v1.x); d1[1] = dup2(v1.y); d1[2] = dup2(v1.z); d1[3] = dup2(v1.w);
        }
        __syncthreads();

        u64 aA00 = x00, aA01 = x01, aA10 = x10, aA11 = x11;
        u64 aB00 = 0, aB01 = 0, aB10 = 0, aB11 = 0;

        // -- shared h0[t] part from SMEM: feeds A (Whh0/Wah0) and B (Wih1/Wax1) --
        {
            const u64* hp  = sh0 + kh * NBAT + bp * 2;
            const u64* wpa = wAs + (In + kh) * NCOL + cp * 2;
            const u64* wpb = wBs + kh * NCOL + cp * 2;
            if (doA && doB) {
#pragma unroll 8
                for (int k = 0; k < 16; k++) {
                    ulonglong2 sv = *(const ulonglong2*)(hp + k * NBAT);
                    ulonglong2 wa = *(const ulonglong2*)(wpa + k * NCOL);
                    ulonglong2 wb = *(const ulonglong2*)(wpb + k * NCOL);
                    fma2(aA00, sv.x, wa.x); fma2(aA01, sv.x, wa.y);
                    fma2(aA10, sv.y, wa.x); fma2(aA11, sv.y, wa.y);
                    fma2(aB00, sv.x, wb.x); fma2(aB01, sv.x, wb.y);
                    fma2(aB10, sv.y, wb.x); fma2(aB11, sv.y, wb.y);
                }
            } else if (doA) {
#pragma unroll 8
                for (int k = 0; k < 16; k++) {
                    ulonglong2 sv = *(const ulonglong2*)(hp + k * NBAT);
                    ulonglong2 wa = *(const ulonglong2*)(wpa + k * NCOL);
                    fma2(aA00, sv.x, wa.x); fma2(aA01, sv.x, wa.y);
                    fma2(aA10, sv.y, wa.x); fma2(aA11, sv.y, wa.y);
                }
            } else {
#pragma unroll 8
                for (int k = 0; k < 16; k++) {
                    ulonglong2 sv = *(const ulonglong2*)(hp + k * NBAT);
                    ulonglong2 wb = *(const ulonglong2*)(wpb + k * NCOL);
                    fma2(aB00, sv.x, wb.x); fma2(aB01, sv.x, wb.y);
                    fma2(aB10, sv.y, wb.x); fma2(aB11, sv.y, wb.y);
                }
            }
        }

        // -- h1[t-1] part (B) from SMEM --
        if (doB) {
            const u64* hp = sh1 + kh * NBAT + bp * 2;
            const u64* wp = wBs + (Hn + kh) * NCOL + cp * 2;
#pragma unroll 8
            for (int k = 0; k < 16; k++) {
                ulonglong2 sv = *(const ulonglong2*)(hp + k * NBAT);
                ulonglong2 wv = *(const ulonglong2*)(wp + k * NCOL);
                fma2(aB00, sv.x, wv.x); fma2(aB01, sv.x, wv.y);
                fma2(aB10, sv.y, wv.x); fma2(aB11, sv.y, wv.y);
            }
        }

        // -- stage partials --
        {
            u64* rr = red + tid * RSTRIDE;
            *(ulonglong2*)(rr + 0) = make_ulonglong2(aA00, aA01);
            *(ulonglong2*)(rr + 2) = make_ulonglong2(aA10, aA11);
            *(ulonglong2*)(rr + 4) = make_ulonglong2(aB00, aB01);
            *(ulonglong2*)(rr + 6) = make_ulonglong2(aB10, aB11);
        }
        __syncthreads();

        // -- reduce + epilogue (tid<256); others go prefetch x --
        if (tid < 256 && (rp ? doB : doA)) {
            u64 acc0 = sbias[rp * NCOL + rc];
            u64 acc1 = 0;
#pragma unroll
            for (int ww = 0; ww < 16; ww += 2) {
                acc0 = add2(acc0, red[(ww * 32 + ridx) * RSTRIDE + raid]);
                acc1 = add2(acc1, red[((ww + 1) * 32 + ridx) * RSTRIDE + raid]);
            }
            u64 acc = add2(acc0, acc1);
            float cnd = lo2(acc), alp = hi2(acc);
            float tv = 1.0f - __fdividef(2.0f, __expf(2.0f * cnd) + 1.0f);
            float sg = __fdividef(1.0f, 1.0f + __expf(-alp));
            float hn = fmaf(sg, tv - hprev, hprev);
            hprev = hn;
            const int C = col0 + rc, B = b0g + rb;
            if (rp == 0) {
                stcgf(&g_h0[((s & 1) * Hn + C) * Bn + B], hn);
            } else {
                stcgf(&g_h1[((t & 1) * Hn + C) * Bn + B], hn);
                out[((size_t)B * Tn + t) * Hn + C] = hn;
            }
        }

        // -- prefetch x-part for step t+2 (fills barrier window) --
        x00 = 0; x01 = 0; x10 = 0; x11 = 0;
        if (t + 2 < Tn) xpart(t + 2, x00, x01, x10, x11);

        grid_barrier(GCTA * bar); bar++;
    }

    // ---- h_final: [2][B][H] appended after outputs ----
    if (tid < 256) {
        const int l = tid >> 7, r = tid & 127;
        const int b = r >> 4, c = r & 15;
        const int C = col0 + c, B = b0g + b;
        const float* src = l ? &g_h1[(1 * Hn + C) * Bn + B]
                             : &g_h0[(1 * Hn + C) * Bn + B];   // (Tn-1)&1 == 1
        out[(size_t)Bn * Tn * Hn + (size_t)l * Bn * Hn + (size_t)B * Hn + C] = *src;
    }
}

// ---------------- launch ----------------
extern "C" void kernel_launch(void* const* d_in, const int* in_sizes, int n_in,
                              void* d_out, int out_size) {
    const float* x    = (const float*)d_in[0];
    const float* Wih0 = (const float*)d_in[1];
    const float* Whh0 = (const float*)d_in[2];
    const float* bh0  = (const float*)d_in[3];
    const float* Wax0 = (const float*)d_in[4];
    const float* Wah0 = (const float*)d_in[5];
    const float* ba0  = (const float*)d_in[6];
    const float* Wih1 = (const float*)d_in[7];
    const float* Whh1 = (const float*)d_in[8];
    const float* bh1  = (const float*)d_in[9];
    const float* Wax1 = (const float*)d_in[10];
    const float* Wah1 = (const float*)d_in[11];
    const float* ba1  = (const float*)d_in[12];
    float* out = (float*)d_out;

    const int smem = (KA + KB) * NCOL * 8        // weights
                   + 2 * Hn * NBAT * 8           // sh0 + sh1
                   + THREADS * RSTRIDE * 8       // red
                   + 2 * NCOL * 8;               // bias
    cudaFuncSetAttribute(rnn_kernel, cudaFuncAttributeMaxDynamicSharedMemorySize, smem);

    prep_kernel<<<Tn, PT>>>(x);
    rnn_kernel<<<GCTA, THREADS, smem>>>(
        Wih0, Whh0, bh0, Wax0, Wah0, ba0,
        Wih1, Whh1, bh1, Wax1, Wah1, ba1,
        out);
}